// round 6
// baseline (speedup 1.0000x reference)
#include <cuda_runtime.h>
#include <cstdint>
#include <cstddef>

#define NVEC 1024
#define NDIM 64
#define NHID 32
#define NW   10
#define NB   16
#define NOFF 11

// Scratch (no allocations allowed): device globals.
__device__ float g_w[NW * NB * NOFF * NVEC];   // sparse W values [i][b][o][n]
__device__ float g_H[NW * NB * NVEC * NHID];   // gelu hidden activations (21MB)
__device__ float g_fW2T[NW * NVEC * NHID];     // fW2 transposed [i][n][h]
__device__ float g_fWT3[10 * 16 * NVEC * 4];   // finW as [c][dg][n][4] (2.6MB)
__device__ float g_part[NB * 8 * 10];          // partial sums for output GEMM
__device__ int   g_cnt;                        // block completion counter

// ---------- f32x2 packed helpers (sm_103a FFMA2) ----------
__device__ __forceinline__ unsigned long long pack2(float x, float y) {
    unsigned long long r;
    asm("mov.b64 %0, {%1, %2};" : "=l"(r) : "f"(x), "f"(y));
    return r;
}
__device__ __forceinline__ void fma2(unsigned long long& d, unsigned long long a, unsigned long long b) {
    asm("fma.rn.f32x2 %0, %1, %2, %0;" : "+l"(d) : "l"(a), "l"(b));
}
__device__ __forceinline__ float2 unpack2(unsigned long long v) {
    float lo, hi;
    asm("mov.b64 {%0, %1}, %2;" : "=f"(lo), "=f"(hi) : "l"(v));
    return make_float2(lo, hi);
}
__device__ __forceinline__ float gelu_exact(float x) {
    return 0.5f * x * (1.0f + erff(x * 0.70710678f));
}

// ---------------------------------------------------------------------------
// Kernel A: H = gelu(X @ fW1 + fb1), register-tiled 8n x 8h, 128 threads
// (z = 0..9).  z == 10: transpose fW2 -> g_fW2T.  z == 11: finW -> g_fWT3.
// ---------------------------------------------------------------------------
#define XS 65
#define H_SMEM ((NDIM * NHID + NHID + 256 * XS) * 4)   // 74880 B

__global__ void __launch_bounds__(128, 3) h_kernel(
    const float* __restrict__ data, const float* __restrict__ fW1,
    const float* __restrict__ fb1,  const float* __restrict__ fW2,
    const float* __restrict__ finW)
{
    extern __shared__ float sm[];
    const int t = threadIdx.x;

    // ---------------- fW2 transpose branch ----------------
    if (blockIdx.z == NW) {
        int idx = blockIdx.y * 4 + blockIdx.x;     // 0..63
        if (idx >= 2 * NW) return;
        const int i  = idx >> 1;
        const int c0 = (idx & 1) * 512;
        float* tile = sm;                          // [32][33]
        for (int s = 0; s < 16; s++) {
#pragma unroll
            for (int it = 0; it < 8; it++) {
                int r = it * 4 + (t >> 5);
                int c = t & 31;
                tile[r * 33 + c] = fW2[((size_t)(i * NHID) + r) * NVEC + c0 + s * 32 + c];
            }
            __syncthreads();
#pragma unroll
            for (int it2 = 0; it2 < 2; it2++) {
                int tt = t + 128 * it2;
                int cr = tt >> 3, rg = tt & 7;
                float4 v = make_float4(tile[(4 * rg + 0) * 33 + cr],
                                       tile[(4 * rg + 1) * 33 + cr],
                                       tile[(4 * rg + 2) * 33 + cr],
                                       tile[(4 * rg + 3) * 33 + cr]);
                *reinterpret_cast<float4*>(
                    &g_fW2T[((size_t)(i * NVEC) + c0 + s * 32 + cr) * NHID + 4 * rg]) = v;
            }
            __syncthreads();
        }
        return;
    }

    // ---------------- finW transpose branch: [f][10] -> [c][dg][n][4] -------
    if (blockIdx.z == NW + 1) {
        int idx = blockIdx.y * 4 + blockIdx.x;     // 0..63
        const int n0 = idx * 16;                   // 16 n-rows = 1024 f-values
        float* sF = sm;                            // [(d*16+nn)][11] layout
        const float4* src =
            reinterpret_cast<const float4*>(finW + (size_t)idx * 10240);
#pragma unroll
        for (int j = 0; j < 20; j++) {             // 2560 float4
            int p = t + 128 * j;
            float4 v = __ldg(src + p);
            float vals[4] = {v.x, v.y, v.z, v.w};
#pragma unroll
            for (int u = 0; u < 4; u++) {
                int e  = 4 * p + u;
                int fl = e / 10, c = e - 10 * fl;
                int d  = fl & 63, nn = fl >> 6;
                sF[(d * 16 + nn) * 11 + c] = vals[u];
            }
        }
        __syncthreads();
        float4* dst = reinterpret_cast<float4*>(g_fWT3);
#pragma unroll
        for (int j = 0; j < 20; j++) {
            int oi = t + 128 * j;                  // 2560 outputs
            int c  = oi >> 8;
            int rem = oi & 255;
            int dg = rem >> 4, nn = rem & 15;
            float4 v;
            v.x = sF[((4 * dg + 0) * 16 + nn) * 11 + c];
            v.y = sF[((4 * dg + 1) * 16 + nn) * 11 + c];
            v.z = sF[((4 * dg + 2) * 16 + nn) * 11 + c];
            v.w = sF[((4 * dg + 3) * 16 + nn) * 11 + c];
            dst[(c * 16 + dg) * 1024 + n0 + nn] = v;
        }
        return;
    }

    // ---------------- H branch ----------------
    float* sw1  = sm;                   // [64][32]
    float* sfb1 = sw1 + NDIM * NHID;    // [32]
    float* Xs   = sfb1 + NHID;          // [256][65]

    const int n0 = blockIdx.x * 256;
    const int b  = blockIdx.y;
    const int i  = blockIdx.z;

    for (int idx = t; idx < NDIM * NHID; idx += 128)
        sw1[idx] = fW1[i * NDIM * NHID + idx];
    if (t < NHID) sfb1[t] = fb1[i * NHID + t];

    const float4* src =
        reinterpret_cast<const float4*>(data + ((size_t)b * NVEC + n0) * NDIM);
#pragma unroll
    for (int j = 0; j < 32; j++) {
        int p  = t + 128 * j;
        int n  = p >> 4;
        int kq = p & 15;
        float4 v = __ldg(src + p);
        float* dst = Xs + n * XS + kq * 4;
        dst[0] = v.x; dst[1] = v.y; dst[2] = v.z; dst[3] = v.w;
    }
    __syncthreads();

    const int ht8 = (t & 3) * 8;
    const int nb  = (t >> 2) * 8;       // 32 groups x 8 rows = 256 n

    unsigned long long acc[8][4];
    {
        const unsigned long long* bp =
            reinterpret_cast<const unsigned long long*>(&sfb1[ht8]);
        unsigned long long b0 = bp[0], b1 = bp[1], b2 = bp[2], b3 = bp[3];
#pragma unroll
        for (int j = 0; j < 8; j++) {
            acc[j][0] = b0; acc[j][1] = b1; acc[j][2] = b2; acc[j][3] = b3;
        }
    }
#pragma unroll 4
    for (int k = 0; k < NDIM; k++) {
        const unsigned long long* wp =
            reinterpret_cast<const unsigned long long*>(&sw1[k * NHID + ht8]);
        unsigned long long w0 = wp[0], w1 = wp[1], w2 = wp[2], w3 = wp[3];
#pragma unroll
        for (int j = 0; j < 8; j++) {
            float xv = Xs[(nb + j) * XS + k];
            unsigned long long xx = pack2(xv, xv);
            fma2(acc[j][0], xx, w0);
            fma2(acc[j][1], xx, w1);
            fma2(acc[j][2], xx, w2);
            fma2(acc[j][3], xx, w3);
        }
    }

    float* Hbase = g_H + ((size_t)(i * NB + b) * NVEC) * NHID;
#pragma unroll
    for (int j = 0; j < 8; j++) {
        float2 v0 = unpack2(acc[j][0]);
        float2 v1 = unpack2(acc[j][1]);
        float2 v2 = unpack2(acc[j][2]);
        float2 v3 = unpack2(acc[j][3]);
        float4 a = make_float4(gelu_exact(v0.x), gelu_exact(v0.y),
                               gelu_exact(v1.x), gelu_exact(v1.y));
        float4 c = make_float4(gelu_exact(v2.x), gelu_exact(v2.y),
                               gelu_exact(v3.x), gelu_exact(v3.y));
        float* dst = Hbase + (size_t)(n0 + nb + j) * NHID + ht8;
        reinterpret_cast<float4*>(dst)[0] = a;
        reinterpret_cast<float4*>(dst)[1] = c;
    }
}

// ---------------------------------------------------------------------------
// Kernel B: sparse W values. Block = (b, i), 1024 threads (t = n), 160 blocks
// (full chip). fW2T ring staged once per block.
// ---------------------------------------------------------------------------
#define FTS 36
#define W2_SMEM ((NVEC * FTS + NVEC) * 4)   // 151552 B

__global__ void __launch_bounds__(1024) w2_kernel(const float* __restrict__ fb2)
{
    extern __shared__ float sm[];
    float* sfT  = sm;              // [1024][36]
    float* sfb2 = sm + NVEC * FTS; // [1024]

    const int t = threadIdx.x;
    const int b = blockIdx.x;
    const int i = blockIdx.y;

    const float4* src4 =
        reinterpret_cast<const float4*>(g_fW2T + (size_t)i * NVEC * NHID);
#pragma unroll
    for (int q = 0; q < 8; q++) {
        int p = t + 1024 * q;
        float4 v = src4[p];
        int n = p >> 3, c = (p & 7) << 2;
        *reinterpret_cast<float4*>(&sfT[n * FTS + c]) = v;
    }
    sfb2[t] = __ldg(&fb2[i * NVEC + t]);

    float h[32];
    {
        const float4* hp = reinterpret_cast<const float4*>(
            g_H + ((size_t)(i * NB + b) * NVEC + t) * NHID);
#pragma unroll
        for (int q = 0; q < 8; q++) {
            float4 v = __ldg(hp + q);
            h[4 * q] = v.x; h[4 * q + 1] = v.y; h[4 * q + 2] = v.z; h[4 * q + 3] = v.w;
        }
    }
    __syncthreads();

    const int OFF[NOFF] = {0, 1, 2, 4, 8, 16, 32, 64, 128, 256, 512};
    float* out = g_w + (size_t)((i * NB + b) * NOFF) * NVEC + t;
#pragma unroll
    for (int o = 0; o < NOFF; o++) {
        int m = (t + OFF[o]) & (NVEC - 1);
        const float4* rp = reinterpret_cast<const float4*>(&sfT[m * FTS]);
        float s0 = 0.f, s1 = 0.f, s2 = 0.f, s3 = 0.f;
#pragma unroll
        for (int q = 0; q < 8; q++) {
            float4 w = rp[q];
            s0 = fmaf(h[4 * q],     w.x, s0);
            s1 = fmaf(h[4 * q + 1], w.y, s1);
            s2 = fmaf(h[4 * q + 2], w.z, s2);
            s3 = fmaf(h[4 * q + 3], w.w, s3);
        }
        out[(size_t)o * NVEC] = (s0 + s1) + (s2 + s3) + sfb2[m];
    }
}

// ---------------------------------------------------------------------------
// Kernel 2: 10-layer sparse recursion + FUSED output GEMM epilogue.
// After the last layer, each thread holds V[t][d0..d0+7] in registers and
// dots against g_fWT3 (coalesced LDG.128). Block reduction -> g_part; the
// last block (counter) performs the deterministic final sum.
// ---------------------------------------------------------------------------
__global__ void __launch_bounds__(1024) recurse_kernel(
    const float* __restrict__ data, const float* __restrict__ finb,
    float* __restrict__ out)
{
    __shared__ float Vs[2][8 * NVEC];
    __shared__ int isLast;
    const int t  = threadIdx.x;
    const int d0 = blockIdx.x * 8;
    const int b  = blockIdx.y;

    const float4* p =
        reinterpret_cast<const float4*>(data + ((size_t)(b * NVEC) + t) * NDIM + d0);
    float4 A  = __ldg(p);
    float4 Bv = __ldg(p + 1);
    float acc[8] = {A.x, A.y, A.z, A.w, Bv.x, Bv.y, Bv.z, Bv.w};
#pragma unroll
    for (int d = 0; d < 8; d++) Vs[0][d * NVEC + t] = acc[d];

    const int OFF[NOFF] = {0, 1, 2, 4, 8, 16, 32, 64, 128, 256, 512};
    float wv[NOFF];
    {
        const float* w = g_w + (size_t)((9 * NB + b) * NOFF) * NVEC;
#pragma unroll
        for (int o = 0; o < NOFF; o++) wv[o] = __ldg(&w[o * NVEC + t]);
    }
    __syncthreads();

    int cur = 0;
#pragma unroll
    for (int i = NW - 1; i >= 0; i--) {
        float wn[NOFF];
        if (i > 0) {
            const float* w = g_w + (size_t)(((i - 1) * NB + b) * NOFF) * NVEC;
#pragma unroll
            for (int o = 0; o < NOFF; o++) wn[o] = __ldg(&w[o * NVEC + t]);
        }

        float na[8];
#pragma unroll
        for (int d = 0; d < 8; d++)
            na[d] = acc[d] + wv[0] * acc[d];
#pragma unroll
        for (int o = 1; o < NOFF; o++) {
            int m = (t + OFF[o]) & (NVEC - 1);
#pragma unroll
            for (int d = 0; d < 8; d++) na[d] += wv[o] * Vs[cur][d * NVEC + m];
        }
#pragma unroll
        for (int d = 0; d < 8; d++) {
            Vs[cur ^ 1][d * NVEC + t] = na[d];
            acc[d] = na[d];
        }
        __syncthreads();
        cur ^= 1;
#pragma unroll
        for (int o = 0; o < NOFF; o++) wv[o] = wn[o];
    }

    // ---- fused output GEMM: cs[c] = sum_d V[t][d0+d] * finW[t*64+d0+d][c] ----
    const float4* W3 = reinterpret_cast<const float4*>(g_fWT3);
    const int dg0 = blockIdx.x * 2;
    float cs[10];
#pragma unroll
    for (int c = 0; c < 10; c++) {
        float4 w0 = __ldg(&W3[(c * 16 + dg0) * 1024 + t]);
        float4 w1 = __ldg(&W3[(c * 16 + dg0 + 1) * 1024 + t]);
        float s = acc[0] * w0.x + acc[1] * w0.y + acc[2] * w0.z + acc[3] * w0.w;
        s += acc[4] * w1.x + acc[5] * w1.y + acc[6] * w1.z + acc[7] * w1.w;
        cs[c] = s;
    }

#pragma unroll
    for (int c = 0; c < 10; c++) {
#pragma unroll
        for (int s = 16; s > 0; s >>= 1)
            cs[c] += __shfl_xor_sync(0xffffffffu, cs[c], s);
    }
    float* red = &Vs[0][0];          // reuse smem (safe: barrier above)
    int lane = t & 31, wp = t >> 5;
    if (lane == 0) {
#pragma unroll
        for (int c = 0; c < 10; c++) red[wp * 10 + c] = cs[c];
    }
    __syncthreads();
    if (t < 10) {
        float s = 0.f;
        for (int w_ = 0; w_ < 32; w_++) s += red[w_ * 10 + t];
        g_part[(b * 8 + blockIdx.x) * 10 + t] = s;
    }
    __threadfence();
    if (t == 0) {
        int old = atomicAdd(&g_cnt, 1);
        isLast = (old == NB * 8 - 1);
    }
    __syncthreads();
    if (isLast) {
        __threadfence();
        if (t == 0) g_cnt = 0;
        if (t < NB * 10) {
            int bb = t / 10, c = t - bb * 10;
            float s = __ldg(&finb[c]);
#pragma unroll
            for (int cc = 0; cc < 8; cc++) s += g_part[(bb * 8 + cc) * 10 + c];
            out[t] = s;
        }
    }
}

// ---------------------------------------------------------------------------
extern "C" void kernel_launch(void* const* d_in, const int* in_sizes, int n_in,
                              void* d_out, int out_size)
{
    const float* data = (const float*)d_in[0];
    const float* fW1  = (const float*)d_in[1];
    const float* fb1  = (const float*)d_in[2];
    const float* fW2  = (const float*)d_in[3];
    const float* fb2  = (const float*)d_in[4];
    const float* finW = (const float*)d_in[5];
    const float* finb = (const float*)d_in[6];
    float* out = (float*)d_out;

    cudaFuncSetAttribute(h_kernel,
                         cudaFuncAttributeMaxDynamicSharedMemorySize, H_SMEM);
    cudaFuncSetAttribute(w2_kernel,
                         cudaFuncAttributeMaxDynamicSharedMemorySize, W2_SMEM);

    h_kernel<<<dim3(4, 16, 12), 128, H_SMEM>>>(data, fW1, fb1, fW2, finW);
    w2_kernel<<<dim3(16, 10), 1024, W2_SMEM>>>(fb2);
    recurse_kernel<<<dim3(8, 16), 1024>>>(data, finb, out);
}